// round 2
// baseline (speedup 1.0000x reference)
#include <cuda_runtime.h>
#include <math.h>

#define B   512
#define TP  256
#define TFD 64
#define DF  64
#define DS  32
#define DM  512
#define NE  6
#define NPAIR 532   // 4*6 + 508

// ---------------- device scratch (no allocations allowed) ----------------
__device__ float g_ab[1000];
__device__ float g_gctx[B*DM];
__device__ float g_temb[B*DM];
__device__ float g_probs[B*NE];
__device__ int   g_sel[B];
__device__ float g_loss[B];
__device__ float g_outsub[NE*4*TFD*DF];   // 98304 floats

__device__ __forceinline__ float gelu_f(float x){
    // jax.nn.gelu default: tanh approximation
    float inner = 0.7978845608028654f*(x + 0.044715f*x*x*x);
    return 0.5f*x*(1.0f + tanhf(inner));
}

// ---------------- K0: alphas_bar cumprod ----------------
__global__ void k_init(){
    if (threadIdx.x == 0){
        float ab = 1.0f;
        const float step = (0.02f - 0.0001f) / 999.0f;
        for (int i = 0; i < 1000; i++){
            float beta = 0.0001f + step * (float)i;
            ab *= (1.0f - beta);
            g_ab[i] = ab;
        }
    }
}

// ---------------- K1: sinusoidal time embedding ----------------
__global__ void k_temb(const int* __restrict__ t){
    int b = blockIdx.x;
    float tv = (float)t[b];
    for (int j = threadIdx.x; j < DM; j += blockDim.x){
        int i = (j < 256) ? j : (j - 256);
        float freq = expf(-9.210340371976184f * (float)i / 256.0f); // ln(10000)
        float a = tv * freq;
        g_temb[b*DM + j] = (j < 256) ? sinf(a) : cosf(a);
    }
}

// ---------------- K2: fused ctx GEMM + gelu + mean over Tp ----------------
// grid (4 jtiles, 512 samples), 128 threads; thread owns one j-column
__global__ void k_ctx(const float* __restrict__ obs, const float* __restrict__ sc,
                      const float* __restrict__ Wenc, const float* __restrict__ benc,
                      const float* __restrict__ Wstat){
    __shared__ float obs_s[8][64];
    int b = blockIdx.y;
    int j = blockIdx.x*128 + threadIdx.x;

    float wcol[64];
    #pragma unroll
    for (int k = 0; k < 64; k++) wcol[k] = Wenc[k*DM + j];

    float pre = benc[j];
    #pragma unroll
    for (int k = 0; k < 32; k++) pre = fmaf(sc[b*DS + k], Wstat[k*DM + j], pre);

    float sum = 0.0f;
    const float* ob = obs + (size_t)b*TP*DF;
    for (int tp0 = 0; tp0 < TP; tp0 += 8){
        __syncthreads();
        #pragma unroll
        for (int i = 0; i < 4; i++){
            int lin = threadIdx.x + i*128;
            obs_s[lin>>6][lin&63] = ob[(tp0 + (lin>>6))*DF + (lin&63)];
        }
        __syncthreads();
        #pragma unroll
        for (int r = 0; r < 8; r++){
            float acc = pre;
            #pragma unroll
            for (int k = 0; k < 64; k += 4){
                float4 v = *(const float4*)&obs_s[r][k];
                acc = fmaf(v.x, wcol[k  ], acc);
                acc = fmaf(v.y, wcol[k+1], acc);
                acc = fmaf(v.z, wcol[k+2], acc);
                acc = fmaf(v.w, wcol[k+3], acc);
            }
            sum += gelu_f(acc);
        }
    }
    g_gctx[b*DM + j] = sum * (1.0f/256.0f);
}

// ---------------- K3: router logits + softmax + selection ----------------
__global__ void k_router(const float* __restrict__ Wr, const float* __restrict__ br,
                         const int* __restrict__ phase){
    int b = blockIdx.x;
    int lane = threadIdx.x;
    float p[6] = {0,0,0,0,0,0};
    for (int k = lane; k < DM; k += 32){
        float g = g_gctx[b*DM + k];
        const float* w = Wr + k*NE;
        #pragma unroll
        for (int e = 0; e < 6; e++) p[e] = fmaf(g, w[e], p[e]);
    }
    #pragma unroll
    for (int off = 16; off; off >>= 1){
        #pragma unroll
        for (int e = 0; e < 6; e++) p[e] += __shfl_xor_sync(0xffffffff, p[e], off);
    }
    if (lane == 0){
        float l[6], pr[6];
        #pragma unroll
        for (int e = 0; e < 6; e++) l[e] = p[e] + br[e];
        float m = l[0];
        #pragma unroll
        for (int e = 1; e < 6; e++) m = fmaxf(m, l[e]);
        float s = 0.0f;
        #pragma unroll
        for (int e = 0; e < 6; e++){ pr[e] = expf(l[e] - m); s += pr[e]; }
        float inv = 1.0f / s;
        #pragma unroll
        for (int e = 0; e < 6; e++){ pr[e] *= inv; g_probs[b*NE + e] = pr[e]; }
        int pl = phase[b];
        g_sel[b] = pl + ((pr[pl+3] > pr[pl]) ? 3 : 0); // argmax ties -> first
    }
}

// ---------------- K4: per-(sample,expert) MLP + per-sample loss + out_sub ----------------
// pair p: p<24 -> (b=p/6, e=p%6) ; else b=p-20, e=selected[b]
__global__ void k_expert(const float* __restrict__ fut, const float* __restrict__ eps,
                         const int* __restrict__ t,
                         const float* __restrict__ W1, const float* __restrict__ b1,
                         const float* __restrict__ W2, const float* __restrict__ b2){
    extern __shared__ float smf[];
    float* gt   = smf;               // 1024
    float* base = gt + 1024;         // 512
    float* nz   = base + 512;        // 4096
    float* hs   = nz + 4096;         // 32*516 (padded vs bank conflicts)
    float* w2c  = hs + 32*516;       // 4096
    __shared__ float red[8];

    int p = blockIdx.x;
    int b, e;
    if (p < 24){ b = p / 6; e = p - b*6; }
    else       { b = p - 20; e = g_sel[p - 20]; }
    int tid = threadIdx.x;
    bool do_loss  = (e == g_sel[b]);
    bool do_store = (b < 4);

    float ab = g_ab[t[b]];
    float sa = sqrtf(ab), sb = sqrtf(1.0f - ab);

    for (int i = tid; i < DM; i += 256){ gt[i] = g_gctx[b*DM + i]; gt[DM + i] = g_temb[b*DM + i]; }
    {
        const float* fb = fut + (size_t)b*TFD*DF;
        const float* eb = eps + (size_t)b*TFD*DF;
        for (int i = tid; i < TFD*DF; i += 256) nz[i] = sa*fb[i] + sb*eb[i];
    }
    __syncthreads();

    const float* W1e = W1 + (size_t)e*1088*512;
    const float* W2e = W2 + (size_t)e*512*64;

    // base[h] = b1 + gctx @ W1[64:576] + temb @ W1[576:1088]
    {
        int h0 = 2*tid;
        float a0 = b1[e*512 + h0], a1 = b1[e*512 + h0 + 1];
        #pragma unroll 8
        for (int k = 0; k < 1024; k++){
            float g = gt[k];
            float2 w = *(const float2*)&W1e[(size_t)(64 + k)*512 + h0];
            a0 = fmaf(g, w.x, a0);
            a1 = fmaf(g, w.y, a1);
        }
        base[h0] = a0; base[h0+1] = a1;
    }
    __syncthreads();

    float lsum = 0.0f;
    int lf0 = 2*(tid >> 4);
    int f0  = 4*(tid & 15);

    for (int th = 0; th < 2; th++){           // two tf-halves of 32
        // phase1: hs[tf][h] = gelu(noisy @ W1[:64] + base)
        for (int hc = 0; hc < 2; hc++){
            int h = tid + hc*256;
            float wa[64];
            #pragma unroll
            for (int k = 0; k < 64; k++) wa[k] = W1e[k*512 + h];
            float bh = base[h];
            #pragma unroll 2
            for (int tf = 0; tf < 32; tf++){
                const float* x = &nz[(th*32 + tf)*64];
                float acc = bh;
                #pragma unroll
                for (int k = 0; k < 64; k += 4){
                    float4 v = *(const float4*)&x[k];
                    acc = fmaf(v.x, wa[k  ], acc);
                    acc = fmaf(v.y, wa[k+1], acc);
                    acc = fmaf(v.z, wa[k+2], acc);
                    acc = fmaf(v.w, wa[k+3], acc);
                }
                hs[tf*516 + h] = gelu_f(acc);
            }
        }
        __syncthreads();

        // phase2: out = hs @ W2 (register-tiled 2tf x 4f, W2 staged in smem chunks)
        float acc[2][4];
        #pragma unroll
        for (int i2 = 0; i2 < 2; i2++)
            #pragma unroll
            for (int jj = 0; jj < 4; jj++) acc[i2][jj] = 0.0f;

        for (int ch = 0; ch < 8; ch++){
            for (int i = tid; i < 4096; i += 256) w2c[i] = W2e[ch*4096 + i];
            __syncthreads();
            #pragma unroll 4
            for (int hh = 0; hh < 64; hh++){
                float a0 = hs[ lf0     *516 + ch*64 + hh];
                float a1 = hs[(lf0 + 1)*516 + ch*64 + hh];
                float4 w = *(const float4*)&w2c[hh*64 + f0];
                acc[0][0] = fmaf(a0, w.x, acc[0][0]);
                acc[0][1] = fmaf(a0, w.y, acc[0][1]);
                acc[0][2] = fmaf(a0, w.z, acc[0][2]);
                acc[0][3] = fmaf(a0, w.w, acc[0][3]);
                acc[1][0] = fmaf(a1, w.x, acc[1][0]);
                acc[1][1] = fmaf(a1, w.y, acc[1][1]);
                acc[1][2] = fmaf(a1, w.z, acc[1][2]);
                acc[1][3] = fmaf(a1, w.w, acc[1][3]);
            }
            __syncthreads();
        }

        #pragma unroll
        for (int i2 = 0; i2 < 2; i2++){
            int tfg = th*32 + lf0 + i2;
            #pragma unroll
            for (int jj = 0; jj < 4; jj++){
                float o = acc[i2][jj] + b2[e*64 + f0 + jj];
                if (do_store) g_outsub[(((e*4 + b)*TFD) + tfg)*DF + f0 + jj] = o;
                if (do_loss){
                    float d = o - eps[(size_t)b*4096 + tfg*64 + f0 + jj];
                    lsum += d*d;
                }
            }
        }
        __syncthreads();   // hs reused next half
    }

    if (do_loss){   // uniform across block
        #pragma unroll
        for (int off = 16; off; off >>= 1) lsum += __shfl_xor_sync(0xffffffff, lsum, off);
        if ((tid & 31) == 0) red[tid >> 5] = lsum;
        __syncthreads();
        if (tid == 0){
            float tot = 0.0f;
            #pragma unroll
            for (int w = 0; w < 8; w++) tot += red[w];
            g_loss[b] = tot * (1.0f/4096.0f);
        }
    }
}

// ---------------- K5: final scalar assembly ----------------
__global__ void k_final(float* __restrict__ out){
    __shared__ float s_lossw, s_chain, s_smooth;
    __shared__ float s_psum[6];
    __shared__ int   s_cnt[6];
    int tid = threadIdx.x;
    if (tid == 0){ s_lossw = 0.0f; s_chain = 0.0f; s_smooth = 0.0f; }
    if (tid < 6){ s_psum[tid] = 0.0f; s_cnt[tid] = 0; }
    __syncthreads();

    const float PW[3] = {1.0f, 5.0f, 5.0f};
    float lw = 0.0f, lp[6] = {0,0,0,0,0,0};
    int   lc[6] = {0,0,0,0,0,0};
    for (int b = tid; b < B; b += 256){
        int s = g_sel[b];
        lw += g_loss[b] * PW[s % 3];
        lc[s]++;
        #pragma unroll
        for (int e = 0; e < 6; e++) lp[e] += g_probs[b*NE + e];
    }
    atomicAdd(&s_lossw, lw);
    #pragma unroll
    for (int e = 0; e < 6; e++){ atomicAdd(&s_psum[e], lp[e]); atomicAdd(&s_cnt[e], lc[e]); }

    const int pa[7] = {0,1,3,4,0,1,2};
    const int pb[7] = {1,2,4,5,3,4,5};
    float ch = 0.0f;
    for (int i = tid; i < 16384; i += 256){
        #pragma unroll
        for (int q = 0; q < 7; q++){
            float d = g_outsub[pa[q]*16384 + i] - g_outsub[pb[q]*16384 + i];
            ch += d*d;
        }
    }
    atomicAdd(&s_chain, ch);

    float smv = 0.0f;
    for (int i = tid; i < 96768; i += 256){   // 6 * 4 * 63 * 64
        int e  = i / 16128; int r  = i - e*16128;
        int s  = r / 4032;  int r2 = r - s*4032;
        int idx = (e*4 + s)*4096 + r2;
        float d = g_outsub[idx + 64] - g_outsub[idx];
        smv += d*d;
    }
    atomicAdd(&s_smooth, smv);
    __syncthreads();

    if (tid == 0){
        float lb = 0.0f;
        #pragma unroll
        for (int e = 0; e < 6; e++)
            lb += ((float)s_cnt[e] / 512.0f) * (s_psum[e] / 512.0f);
        float total = s_lossw / 512.0f
                    + 0.01f * (s_chain / 16384.0f + 0.5f * s_smooth / 16128.0f)
                    + 0.06f * lb;   // LAMBDA_LB * E
        out[0] = total;
    }
}

// ---------------- launch ----------------
extern "C" void kernel_launch(void* const* d_in, const int* in_sizes, int n_in,
                              void* d_out, int out_size){
    const float* obs  = (const float*)d_in[0];
    const float* fut  = (const float*)d_in[1];
    const float* sc   = (const float*)d_in[2];
    const float* eps  = (const float*)d_in[3];
    const int*   phase= (const int*)  d_in[4];
    const int*   t    = (const int*)  d_in[5];
    const float* Wenc = (const float*)d_in[6];
    const float* benc = (const float*)d_in[7];
    const float* Wstat= (const float*)d_in[8];
    const float* Wr   = (const float*)d_in[9];
    const float* br   = (const float*)d_in[10];
    const float* W1   = (const float*)d_in[11];
    const float* b1   = (const float*)d_in[12];
    const float* W2   = (const float*)d_in[13];
    const float* b2   = (const float*)d_in[14];

    const int SMEM_EXPERT = (1024 + 512 + 4096 + 32*516 + 4096) * 4; // 104960 B
    static bool attr_done = false;   // host-side, idempotent; not device state
    if (!attr_done){
        cudaFuncSetAttribute(k_expert, cudaFuncAttributeMaxDynamicSharedMemorySize, SMEM_EXPERT);
        attr_done = true;
    }

    k_init  <<<1, 32>>>();
    k_temb  <<<B, 256>>>(t);
    k_ctx   <<<dim3(4, B), 128>>>(obs, sc, Wenc, benc, Wstat);
    k_router<<<B, 32>>>(Wr, br, phase);
    k_expert<<<NPAIR, 256, SMEM_EXPERT>>>(fut, eps, t, W1, b1, W2, b2);
    k_final <<<1, 256>>>((float*)d_out);
}